// round 7
// baseline (speedup 1.0000x reference)
#include <cuda_runtime.h>
#include <cstdint>

// Problem constants (match reference_code)
#define N_USER   100000
#define N_ITEM   50000
#define NTOT     150000
#define D        64
#define NNZ_CNT  4000000
#define BATCH    2048
#define NEGS     8192
#define NOUT     (BATCH + BATCH + NEGS)   // 12288
#define BM_WORDS ((NTOT + 31) / 32)       // 4688

#define FULLMASK 0xffffffffu
#define NNZ_PER_BLOCK 2048                // 256 thr * 8 nnz

// Scratch (device globals). Everything we read is re-initialized each launch
// (bitmap, counter, touched acc rows), so graph replays are self-consistent.
__device__ float    g_acc[(size_t)NTOT * D];   // ~38.4 MB
__device__ unsigned g_bm[BM_WORDS];            // ~19 KB
__device__ int      g_rowof[NOUT];
__device__ int      g_nh;                      // hit count
__device__ int4     g_hits[NNZ_CNT];           // {row, col, val_bits, pad}

// ---------------------------------------------------------------------------
// Kernel 1: clear bitmap + hit counter
// ---------------------------------------------------------------------------
__global__ void k_clear()
{
    int i = blockIdx.x * blockDim.x + threadIdx.x;
    if (i < BM_WORDS) g_bm[i] = 0u;
    if (i == 0) g_nh = 0;
}

// ---------------------------------------------------------------------------
// Kernel 2: mark rows, seed g_acc[row] = e0[row]/3, cache resolved row index
// ---------------------------------------------------------------------------
__global__ void k_mark(const int* __restrict__ users,
                       const int* __restrict__ pos,
                       const int* __restrict__ neg,
                       const float* __restrict__ ue,
                       const float* __restrict__ ie)
{
    int tid = blockIdx.x * blockDim.x + threadIdx.x;
    int rowIdx = tid >> 4;
    int l16    = tid & 15;
    if (rowIdx >= NOUT) return;

    int row;
    if (rowIdx < BATCH)            row = users[rowIdx];
    else if (rowIdx < 2 * BATCH)   row = N_USER + pos[rowIdx - BATCH];
    else                           row = N_USER + neg[rowIdx - 2 * BATCH];

    if (l16 == 0) {
        atomicOr(&g_bm[row >> 5], 1u << (row & 31));
        g_rowof[rowIdx] = row;
    }

    const float* src = (row < N_USER)
                     ? (ue + (size_t)row * D)
                     : (ie + (size_t)(row - N_USER) * D);
    float4 e = reinterpret_cast<const float4*>(src)[l16];
    const float k = 1.0f / 3.0f;
    e.x *= k; e.y *= k; e.z *= k; e.w *= k;
    reinterpret_cast<float4*>(g_acc + (size_t)row * D)[l16] = e;
}

// ---------------------------------------------------------------------------
// Kernel 3a: global hit compaction.
// 8 nnz per thread; warp scan of hit counts; shared-aggregated intra-block
// offsets; ONE global atomicAdd per block; coalesced 16B hit-record writes.
// ---------------------------------------------------------------------------
__global__ void k_compact(const int*   __restrict__ rows,
                          const int*   __restrict__ cols,
                          const float* __restrict__ vals)
{
    __shared__ int sh_cnt;
    __shared__ int sh_base;

    const int tid  = threadIdx.x;
    const int lane = tid & 31;
    if (tid == 0) sh_cnt = 0;
    __syncthreads();

    const long myBase = (long)blockIdx.x * NNZ_PER_BLOCK + (long)tid * 8;

    int r[8];
    unsigned mask8 = 0;
    if (myBase < NNZ_CNT) {          // NNZ % 8 == 0: chunk all-in or all-out
        int4 a = *reinterpret_cast<const int4*>(rows + myBase);
        int4 b = *reinterpret_cast<const int4*>(rows + myBase + 4);
        r[0]=a.x; r[1]=a.y; r[2]=a.z; r[3]=a.w;
        r[4]=b.x; r[5]=b.y; r[6]=b.z; r[7]=b.w;
#pragma unroll
        for (int j = 0; j < 8; j++)
            if ((g_bm[r[j] >> 5] >> (r[j] & 31)) & 1u) mask8 |= (1u << j);
    }

    int cnt = __popc(mask8);
    int inc = cnt;
#pragma unroll
    for (int d = 1; d < 32; d <<= 1) {
        int n = __shfl_up_sync(FULLMASK, inc, d);
        if (lane >= d) inc += n;
    }
    int wtotal = __shfl_sync(FULLMASK, inc, 31);
    int wbase  = 0;
    if (lane == 31 && wtotal > 0) wbase = atomicAdd(&sh_cnt, wtotal);
    wbase = __shfl_sync(FULLMASK, wbase, 31);
    int myoff = wbase + inc - cnt;

    __syncthreads();
    if (tid == 0) sh_base = (sh_cnt > 0) ? atomicAdd(&g_nh, sh_cnt) : 0;
    __syncthreads();
    const int gbase = sh_base;

    if (mask8) {
#pragma unroll
        for (int j = 0; j < 8; j++) {
            if ((mask8 >> j) & 1u) {
                int p = gbase + myoff + __popc(mask8 & ((1u << j) - 1u));
                int4 h;
                h.x = r[j];
                h.y = cols[myBase + j];
                h.z = __float_as_int(vals[myBase + j]);
                h.w = 0;
                g_hits[p] = h;
            }
        }
    }
}

// ---------------------------------------------------------------------------
// Kernel 3b: scatter. Half-warp per hit, grid-strided, 2-way unrolled.
// Perfectly balanced, independent iterations -> high MLP.
// ---------------------------------------------------------------------------
__global__ void k_scatter(const float* __restrict__ ue,
                          const float* __restrict__ ie)
{
    const int nh  = g_nh;
    const int l16 = threadIdx.x & 15;
    const int hw  = (blockIdx.x * blockDim.x + threadIdx.x) >> 4;
    const int nhw = (gridDim.x * blockDim.x) >> 4;

    int h = hw;
    for (; h + nhw < nh; h += 2 * nhw) {
        int4 t0 = g_hits[h];
        int4 t1 = g_hits[h + nhw];

        const float* s0 = (t0.y < N_USER) ? (ue + (size_t)t0.y * D)
                                          : (ie + (size_t)(t0.y - N_USER) * D);
        const float* s1 = (t1.y < N_USER) ? (ue + (size_t)t1.y * D)
                                          : (ie + (size_t)(t1.y - N_USER) * D);
        float4 e0 = reinterpret_cast<const float4*>(s0)[l16];
        float4 e1 = reinterpret_cast<const float4*>(s1)[l16];
        float  v0 = __int_as_float(t0.z);
        float  v1 = __int_as_float(t1.z);

        float* d0 = g_acc + (size_t)t0.x * D + l16 * 4;
        float* d1 = g_acc + (size_t)t1.x * D + l16 * 4;
        asm volatile("red.global.add.v4.f32 [%0], {%1, %2, %3, %4};"
                     :: "l"(d0), "f"(e0.x*v0), "f"(e0.y*v0), "f"(e0.z*v0), "f"(e0.w*v0) : "memory");
        asm volatile("red.global.add.v4.f32 [%0], {%1, %2, %3, %4};"
                     :: "l"(d1), "f"(e1.x*v1), "f"(e1.y*v1), "f"(e1.z*v1), "f"(e1.w*v1) : "memory");
    }
    if (h < nh) {
        int4 t = g_hits[h];
        const float* s = (t.y < N_USER) ? (ue + (size_t)t.y * D)
                                        : (ie + (size_t)(t.y - N_USER) * D);
        float4 e = reinterpret_cast<const float4*>(s)[l16];
        float  v = __int_as_float(t.z);
        float* d = g_acc + (size_t)t.x * D + l16 * 4;
        asm volatile("red.global.add.v4.f32 [%0], {%1, %2, %3, %4};"
                     :: "l"(d), "f"(e.x*v), "f"(e.y*v), "f"(e.z*v), "f"(e.w*v) : "memory");
    }
}

// ---------------------------------------------------------------------------
// Kernel 4: out[j] = 0.75 * g_acc[g_rowof[j]], 4 independent rows per thread
// ---------------------------------------------------------------------------
__global__ void k_out(float* __restrict__ out)
{
    int tid  = blockIdx.x * blockDim.x + threadIdx.x;
    int slot = tid >> 4;
    int l16  = tid & 15;
    if (slot >= NOUT / 4) return;

#pragma unroll
    for (int k = 0; k < 4; k++) {
        int rowIdx = slot + k * (NOUT / 4);
        int row = g_rowof[rowIdx];
        float4 a = reinterpret_cast<const float4*>(g_acc + (size_t)row * D)[l16];
        a.x *= 0.75f; a.y *= 0.75f; a.z *= 0.75f; a.w *= 0.75f;
        reinterpret_cast<float4*>(out)[(size_t)rowIdx * (D / 4) + l16] = a;
    }
}

// ---------------------------------------------------------------------------
// Launch
// ---------------------------------------------------------------------------
extern "C" void kernel_launch(void* const* d_in, const int* in_sizes, int n_in,
                              void* d_out, int out_size)
{
    const int*   users = (const int*)  d_in[0];
    const int*   pos   = (const int*)  d_in[1];
    const int*   neg   = (const int*)  d_in[2];
    const float* ue    = (const float*)d_in[5];
    const float* ie    = (const float*)d_in[6];
    const int*   arow  = (const int*)  d_in[7];
    const int*   acol  = (const int*)  d_in[8];
    const float* aval  = (const float*)d_in[9];
    float*       out   = (float*)d_out;

    k_clear<<<(BM_WORDS + 255) / 256, 256>>>();

    k_mark<<<(NOUT * 16 + 255) / 256, 256>>>(users, pos, neg, ue, ie);

    {
        const int blocks = (NNZ_CNT + NNZ_PER_BLOCK - 1) / NNZ_PER_BLOCK; // 1954
        k_compact<<<blocks, 256>>>(arow, acol, aval);
    }

    // 1184 blocks = 8 per SM -> 19K half-warps, grid-strided over ~330K hits
    k_scatter<<<1184, 256>>>(ue, ie);

    k_out<<<(NOUT * 4 + 255) / 256, 256>>>(out);
}